// round 4
// baseline (speedup 1.0000x reference)
#include <cuda_runtime.h>
#include <mma.h>
#include <math.h>

using namespace nvcuda;

#define Bn   128
#define Hn   8
#define Rn   130
#define Tn   256
#define Qd   32
#define BHn  (Bn*Hn)     /* 1024 */
#define Mn   (Bn*Rn)     /* 16640 */
#define NQK  512

// ---------------- device scratch (no allocations allowed) ----------------
__device__ float g_qk[(size_t)Mn*NQK];            // q|k projections (NO bias), [M,512]
__device__ float g_feats[(size_t)BHn*Rn*Tn];      // GCN features (flagged heads only)
__device__ float g_agg[(size_t)BHn*Rn*Tn];        // sparse A @ feats scratch
__device__ float g_spval[BHn*Rn*8];               // sparse A values (pre-gate)
__device__ int   g_spcol[BHn*Rn*8];               // sparse A column indices
__device__ int   g_spcnt[BHn*Rn];                 // nnz per row (6 or 7)
__device__ float g_gap[BHn];                      // sum of rel per (b,h)
__device__ float g_maxA[BHn];                     // max kept rel value per (b,h)
__device__ float g_gate[BHn];                     // SE gate (0 or 1)
__device__ int   g_flag[BHn];                     // gate!=0 && maxA>0
__device__ float g_S[Tn+1];                       // S[t]=sum_i relu(gcn_b[i][t]); S[256]=mean

__global__ void k_nop() {}

// ---------------- K1: qk = x @ [Wq;Wk]^T  (tf32 HMMA) ---------------------
#define XPAD 40
__global__ void __launch_bounds__(256)
k_qkproj(const float* __restrict__ x,
         const float* __restrict__ Wq, const float* __restrict__ Wk)
{
    __shared__ float Xs[128 * XPAD];
    __shared__ float Ws[128 * XPAD];

    int tid = threadIdx.x;
    int wid = tid >> 5;
    int m0 = blockIdx.x * 128, n0 = blockIdx.y * 128;
    int wm = wid >> 2;          // 0..1 : 64-row slice
    int wn = wid & 3;           // 0..3 : 32-col slice

    const float* Wbase = (n0 < 256) ? (Wq + (size_t)n0 * 256)
                                    : (Wk + (size_t)(n0 - 256) * 256);
    const float* Xbase = x + (size_t)m0 * 256;

    wmma::fragment<wmma::accumulator, 16, 16, 8, float> acc[4][2];
    #pragma unroll
    for (int i = 0; i < 4; i++)
        #pragma unroll
        for (int j = 0; j < 2; j++)
            wmma::fill_fragment(acc[i][j], 0.0f);

    for (int k0 = 0; k0 < 256; k0 += 32) {
        #pragma unroll
        for (int i = 0; i < 4; i++) {
            int idx = tid + i * 256;
            int row = idx >> 3;
            int c4  = (idx & 7) * 4;
            *(float4*)&Xs[row * XPAD + c4] =
                *(const float4*)(Xbase + (size_t)row * 256 + k0 + c4);
            *(float4*)&Ws[row * XPAD + c4] =
                *(const float4*)(Wbase + (size_t)row * 256 + k0 + c4);
        }
        __syncthreads();

        #pragma unroll
        for (int kk = 0; kk < 32; kk += 8) {
            wmma::fragment<wmma::matrix_a, 16, 16, 8, wmma::precision::tf32, wmma::row_major> af[4];
            wmma::fragment<wmma::matrix_b, 16, 16, 8, wmma::precision::tf32, wmma::col_major> bf[2];
            #pragma unroll
            for (int i = 0; i < 4; i++) {
                wmma::load_matrix_sync(af[i], &Xs[(wm * 64 + i * 16) * XPAD + kk], XPAD);
                #pragma unroll
                for (int e = 0; e < af[i].num_elements; e++)
                    af[i].x[e] = wmma::__float_to_tf32(af[i].x[e]);
            }
            #pragma unroll
            for (int j = 0; j < 2; j++) {
                wmma::load_matrix_sync(bf[j], &Ws[(wn * 32 + j * 16) * XPAD + kk], XPAD);
                #pragma unroll
                for (int e = 0; e < bf[j].num_elements; e++)
                    bf[j].x[e] = wmma::__float_to_tf32(bf[j].x[e]);
            }
            #pragma unroll
            for (int i = 0; i < 4; i++)
                #pragma unroll
                for (int j = 0; j < 2; j++)
                    wmma::mma_sync(acc[i][j], af[i], bf[j], acc[i][j]);
        }
        __syncthreads();
    }

    #pragma unroll
    for (int i = 0; i < 4; i++)
        #pragma unroll
        for (int j = 0; j < 2; j++) {
            float* dst = g_qk + (size_t)(m0 + wm * 64 + i * 16) * NQK
                              + n0 + wn * 32 + j * 16;
            wmma::store_matrix_sync(dst, acc[i][j], NQK, wmma::mem_row_major);
        }
}

// ---------------- K2: fused rel/softmax/threshold/rank, register-resident --
#define SQS 36
__global__ void __launch_bounds__(256, 3)
k_attn(const float* __restrict__ thr_p,
       const float* __restrict__ bq, const float* __restrict__ bk)
{
    __shared__ float sq[132 * SQS];
    __shared__ float sk[132 * SQS];
    __shared__ float s_gap[8], s_max[8];

    int bh = blockIdx.x, b = bh >> 3, h = bh & 7;
    int tid = threadIdx.x, lane = tid & 31, w = tid >> 5;
    const float thr = *thr_p;

    // load q,k + bias into smem (rows 130,131 zero)
    for (int e = tid; e < 132 * Qd; e += 256) {
        int r = e >> 5, i = e & 31;
        float qv = 0.f, kv = 0.f;
        if (r < Rn) {
            size_t rowb = (size_t)(b * Rn + r) * NQK + h * 32;
            qv = g_qk[rowb + i]       + bq[h * 32 + i];
            kv = g_qk[rowb + 256 + i] + bk[h * 32 + i];
        }
        sq[r * SQS + i] = qv;
        sk[r * SQS + i] = kv;
    }
    __syncthreads();

    float gapAcc = 0.f, maxAcc = 0.f;
    const float sc = 0.17677669529663687f;   // 1/sqrt(32)
    const int cols1 = 4, cols2 = 5, cols3 = 6, cols4 = 7, cols5 = 8;

    for (int g = w; g < 33; g += 8) {
        int r0 = g * 4;
        float acc[4][5];
        #pragma unroll
        for (int rr = 0; rr < 4; rr++)
            #pragma unroll
            for (int jb = 0; jb < 5; jb++) acc[rr][jb] = 0.f;

        // QK^T for 4 rows, lane owns columns jb*32+lane
        #pragma unroll
        for (int jb = 0; jb < 5; jb++) {
            int s = jb * 32 + lane; if (s > 131) s = 131;
            const float* krow = &sk[s * SQS];
            #pragma unroll
            for (int i4 = 0; i4 < 32; i4 += 4) {
                float4 kv = *(const float4*)(krow + i4);
                #pragma unroll
                for (int rr = 0; rr < 4; rr++) {
                    float4 qv = *(const float4*)&sq[(r0 + rr) * SQS + i4];
                    float a = acc[rr][jb];
                    a = fmaf(qv.x, kv.x, a);
                    a = fmaf(qv.y, kv.y, a);
                    a = fmaf(qv.z, kv.z, a);
                    a = fmaf(qv.w, kv.w, a);
                    acc[rr][jb] = a;
                }
            }
        }

        bool val4 = (lane < 2);   // jb=4 true columns: 128,129 only

        #pragma unroll
        for (int rr = 0; rr < 4; rr++) {
            int r = r0 + rr;
            if (r < Rn) {
                float v0 = acc[rr][0] * sc, v1 = acc[rr][1] * sc,
                      v2 = acc[rr][2] * sc, v3 = acc[rr][3] * sc,
                      v4 = acc[rr][4] * sc;
                // softmax
                float m = fmaxf(fmaxf(fmaxf(v0, v1), fmaxf(v2, v3)),
                                val4 ? v4 : -1e30f);
                #pragma unroll
                for (int o = 16; o; o >>= 1) m = fmaxf(m, __shfl_xor_sync(~0u, m, o));
                float e0 = __expf(v0 - m), e1 = __expf(v1 - m),
                      e2 = __expf(v2 - m), e3 = __expf(v3 - m);
                float e4 = val4 ? __expf(v4 - m) : 0.f;
                float se = e0 + e1 + e2 + e3 + e4;
                #pragma unroll
                for (int o = 16; o; o >>= 1) se += __shfl_xor_sync(~0u, se, o);
                float rinv = 1.f / se;
                v0 = fmaxf(fmaf(e0, rinv, -thr), 0.f);
                v1 = fmaxf(fmaf(e1, rinv, -thr), 0.f);
                v2 = fmaxf(fmaf(e2, rinv, -thr), 0.f);
                v3 = fmaxf(fmaf(e3, rinv, -thr), 0.f);
                v4 = val4 ? fmaxf(fmaf(e4, rinv, -thr), 0.f) : 0.f;
                float gs = v0 + v1 + v2 + v3 + v4;
                #pragma unroll
                for (int o = 16; o; o >>= 1) gs += __shfl_xor_sync(~0u, gs, o);

                // ranks of columns {0,4,5,6,7,8} (all live in v0 of lanes 0,4..8)
                float c0 = __shfl_sync(~0u, v0, 0);
                float c1 = __shfl_sync(~0u, v0, cols1);
                float c2 = __shfl_sync(~0u, v0, cols2);
                float c3 = __shfl_sync(~0u, v0, cols3);
                float c4c = __shfl_sync(~0u, v0, cols4);
                float c5 = __shfl_sync(~0u, v0, cols5);

                unsigned p0 = 0, p1 = 0;
                #pragma unroll
                for (int jb = 0; jb < 5; jb++) {
                    int j = jb * 32 + lane;
                    float vv = (jb == 0) ? v0 : (jb == 1) ? v1 : (jb == 2) ? v2
                             : (jb == 3) ? v3 : v4;
                    p0 += (vv > c0)                                   ? 1u        : 0u;
                    p0 += ((vv > c1) || (vv == c1 && j < cols1))      ? (1u<<8)   : 0u;
                    p0 += ((vv > c2) || (vv == c2 && j < cols2))      ? (1u<<16)  : 0u;
                    p0 += ((vv > c3) || (vv == c3 && j < cols3))      ? (1u<<24)  : 0u;
                    p1 += ((vv > c4c)|| (vv == c4c&& j < cols4))      ? 1u        : 0u;
                    p1 += ((vv > c5) || (vv == c5 && j < cols5))      ? (1u<<8)   : 0u;
                }
                #pragma unroll
                for (int o = 16; o; o >>= 1) {
                    p0 += __shfl_xor_sync(~0u, p0, o);
                    p1 += __shfl_xor_sync(~0u, p1, o);
                }
                // lane c (<6) holds rank of cols0[c]
                int myp = (lane < 4) ? (int)((p0 >> (8 * lane)) & 255u)
                                     : (int)((p1 >> (8 * (lane - 4))) & 255u);
                unsigned ball = __ballot_sync(~0u, (lane < 6) && (myp == r));
                int cnt = 6;
                if (!ball) { if (lane == 6) myp = r; cnt = 7; }

                int base = (bh * Rn + r) * 8;
                float rmax = 0.f;
                for (int i = 0; i < cnt; i++) {
                    int p = __shfl_sync(~0u, myp, i);
                    int jbp = p >> 5;
                    float av = (jbp == 0) ? v0 : (jbp == 1) ? v1 : (jbp == 2) ? v2
                             : (jbp == 3) ? v3 : v4;
                    float vv = __shfl_sync(~0u, av, p & 31);
                    if (lane == 0) { g_spcol[base + i] = p; g_spval[base + i] = vv; }
                    rmax = fmaxf(rmax, vv);
                }
                if (lane == 0) {
                    g_spcnt[bh * Rn + r] = cnt;
                    gapAcc += gs;
                    maxAcc = fmaxf(maxAcc, rmax);
                }
            }
        }
    }
    if (lane == 0) { s_gap[w] = gapAcc; s_max[w] = maxAcc; }
    __syncthreads();
    if (tid == 0) {
        float gsum = 0.f, mx = 0.f;
        #pragma unroll
        for (int i = 0; i < 8; i++) { gsum += s_gap[i]; mx = fmaxf(mx, s_max[i]); }
        g_gap[bh] = gsum; g_maxA[bh] = mx;
    }
}

// ---------------- K3: SE gate + flags -------------------------------------
__global__ void k_gate(const float* __restrict__ seW1, const float* __restrict__ seb1,
                       const float* __restrict__ seW2, const float* __restrict__ seb2)
{
    int b = blockIdx.x;
    if (threadIdx.x) return;
    float g[8];
    #pragma unroll
    for (int h = 0; h < 8; h++) g[h] = g_gap[b * 8 + h] * (1.f / 16900.f);
    float hd[4];
    #pragma unroll
    for (int j = 0; j < 4; j++) {
        float a = seb1[j];
        #pragma unroll
        for (int h = 0; h < 8; h++) a = fmaf(seW1[j * 8 + h], g[h], a);
        hd[j] = fmaxf(a, 0.f);
    }
    #pragma unroll
    for (int i = 0; i < 8; i++) {
        float z = seb2[i];
        #pragma unroll
        for (int j = 0; j < 4; j++) z = fmaf(seW2[i * 4 + j], hd[j], z);
        float gt = floorf(1.f / (1.f + expf(-z)));   // .long() truncation
        g_gate[b * 8 + i] = gt;
        g_flag[b * 8 + i] = (gt != 0.f) && (g_maxA[b * 8 + i] > 0.f);
    }
}

// ---------------- Kprep: S[t] = sum_i relu(gcn_b[i][t]) -------------------
__global__ void k_prep(const float* __restrict__ gcn_b)
{
    __shared__ float red[256];
    int t = threadIdx.x;
    float s = 0.f;
    #pragma unroll
    for (int i = 0; i < 8; i++) s += fmaxf(gcn_b[i * 256 + t], 0.f);
    g_S[t] = s;
    red[t] = s; __syncthreads();
    for (int o = 128; o; o >>= 1) { if (t < o) red[t] += red[t + o]; __syncthreads(); }
    if (t == 0) g_S[256] = red[0] * (1.f / 256.f);
}

// ---------------- GCN: all 8 layers, one block per (b,h), flag-guarded ----
__global__ void k_gcnall(const float* __restrict__ x,
                         const float* __restrict__ gcnW, const float* __restrict__ gcnb)
{
    int bh = blockIdx.x;
    if (!g_flag[bh]) return;
    int b = bh >> 3;
    float gt = g_gate[bh];
    size_t base = (size_t)bh * Rn * Tn;
    const float* xb = x + (size_t)b * Rn * Tn;

    for (int e = threadIdx.x; e < Rn * Tn; e += 256) g_feats[base + e] = xb[e];
    __syncthreads();

    for (int L = 0; L < 8; L++) {
        const float* W    = gcnW + (size_t)L * Tn * Tn;
        const float* bias = gcnb + L * Tn;
        for (int e = threadIdx.x; e < Rn * Tn; e += 256) {
            int r = e >> 8, t = e & 255;
            int cnt = g_spcnt[bh * Rn + r];
            int sb  = (bh * Rn + r) * 8;
            float a = 0.f;
            for (int i = 0; i < cnt; i++)
                a = fmaf(g_spval[sb + i],
                         g_feats[base + (size_t)g_spcol[sb + i] * Tn + t], a);
            g_agg[base + e] = a * gt;
        }
        __syncthreads();
        for (int e = threadIdx.x; e < Rn * Tn; e += 256) {
            int r = e >> 8, t = e & 255;
            float acc = bias[t];
            const float* ag = g_agg + base + (size_t)r * Tn;
            const float* wr = W + (size_t)t * Tn;
            for (int u = 0; u < Tn; u++) acc = fmaf(ag[u], wr[u], acc);
            g_feats[base + e] = fmaxf(acc, 0.f) + g_feats[base + e];
        }
        __syncthreads();
    }
}

// ---------------- K5: fusion + pool + MLP head ----------------------------
__global__ void k_head(const float* __restrict__ x,
                       const float* __restrict__ fw, const float* __restrict__ fb,
                       const float* __restrict__ W1, const float* __restrict__ b1,
                       const float* __restrict__ W2, const float* __restrict__ b2,
                       const float* __restrict__ W3, const float* __restrict__ b3,
                       float* __restrict__ out)
{
    int b = blockIdx.x;
    int tid = threadIdx.x, lane = tid & 31, w = tid >> 5;
    __shared__ float pooled[132], sh1[64], sh2[16];
    __shared__ float swf[8];
    __shared__ int   sfl[8];
    if (tid < 8) { swf[tid] = fw[tid]; sfl[tid] = g_flag[b * 8 + tid]; }
    __syncthreads();
    float meanS = g_S[256], fbv = *fb;

    for (int r = w; r < Rn; r += 8) {
        const float* xr = x + ((size_t)b * Rn + r) * Tn;
        float sx = 0.f;
        for (int t = lane; t < Tn; t += 32) sx += xr[t];
        #pragma unroll
        for (int o = 16; o; o >>= 1) sx += __shfl_xor_sync(~0u, sx, o);
        float mx = sx * (1.f / 256.f);
        float acc = fbv;
        #pragma unroll
        for (int h = 0; h < 8; h++) {
            if (sfl[h]) {
                const float* fr = g_feats + ((size_t)(b * 8 + h) * Rn + r) * Tn;
                float sf = 0.f;
                for (int t = lane; t < Tn; t += 32) sf += fr[t];
                #pragma unroll
                for (int o = 16; o; o >>= 1) sf += __shfl_xor_sync(~0u, sf, o);
                acc = fmaf(swf[h], sf * (1.f / 256.f), acc);
            } else {
                acc = fmaf(swf[h], mx + meanS, acc);   // closed form: feats = x + S
            }
        }
        if (lane == 0) pooled[r] = acc;
    }
    __syncthreads();
    if (tid < 64) {
        float a = b1[tid];
        for (int r = 0; r < Rn; r++) a = fmaf(W1[tid * Rn + r], pooled[r], a);
        sh1[tid] = fmaxf(a, 0.f);
    }
    __syncthreads();
    if (tid < 16) {
        float a = b2[tid];
        #pragma unroll
        for (int j = 0; j < 64; j++) a = fmaf(W2[tid * 64 + j], sh1[j], a);
        sh2[tid] = fmaxf(a, 0.f);
    }
    __syncthreads();
    if (tid < 5) {
        float a = b3[tid];
        #pragma unroll
        for (int j = 0; j < 16; j++) a = fmaf(W3[tid * 16 + j], sh2[j], a);
        out[b * 5 + tid] = fmaxf(a, 0.f);
    }
}

// ---------------- launch ---------------------------------------------------
extern "C" void kernel_launch(void* const* d_in, const int* in_sizes, int n_in,
                              void* d_out, int out_size)
{
    const float* x    = (const float*)d_in[0];
    const float* Wq   = (const float*)d_in[1];
    const float* bq   = (const float*)d_in[2];
    const float* Wk   = (const float*)d_in[3];
    const float* bk   = (const float*)d_in[4];
    const float* thr  = (const float*)d_in[5];
    const float* seW1 = (const float*)d_in[6];
    const float* seb1 = (const float*)d_in[7];
    const float* seW2 = (const float*)d_in[8];
    const float* seb2 = (const float*)d_in[9];
    const float* gcnW = (const float*)d_in[10];
    const float* gcnb = (const float*)d_in[11];
    const float* fw   = (const float*)d_in[12];
    const float* fb   = (const float*)d_in[13];
    const float* W1   = (const float*)d_in[14];
    const float* b1   = (const float*)d_in[15];
    const float* W2   = (const float*)d_in[16];
    const float* b2   = (const float*)d_in[17];
    const float* W3   = (const float*)d_in[18];
    const float* b3   = (const float*)d_in[19];
    float* out = (float*)d_out;

    dim3 g1(Mn / 128, NQK / 128);
    k_qkproj<<<g1, 256>>>(x, Wq, Wk);                    // launch 1
    k_prep<<<1, 256>>>(gcnb);                            // launch 2
    k_nop<<<1, 32>>>();                                  // launch 3
    k_attn<<<BHn, 256>>>(thr, bq, bk);                   // launch 4 <- ncu capture
    k_gate<<<Bn, 32>>>(seW1, seb1, seW2, seb2);          // launch 5
    k_gcnall<<<BHn, 256>>>(x, gcnW, gcnb);               // launch 6
    k_head<<<Bn, 256>>>(x, fw, fb, W1, b1, W2, b2, W3, b3, out);  // launch 7
}

// round 5
// speedup vs baseline: 1.3655x; 1.3655x over previous
#include <cuda_runtime.h>
#include <mma.h>
#include <math.h>

using namespace nvcuda;

#define Bn   128
#define Hn   8
#define Rn   130
#define Tn   256
#define Qd   32
#define BHn  (Bn*Hn)     /* 1024 */
#define Mn   (Bn*Rn)     /* 16640 */
#define NQK  512

// ---------------- device scratch (no allocations allowed) ----------------
__device__ float g_qk[(size_t)Mn*NQK];            // q|k projections (NO bias), [M,512]
__device__ float g_feats[(size_t)BHn*Rn*Tn];      // GCN features (flagged heads only)
__device__ float g_agg[(size_t)BHn*Rn*Tn];        // sparse A @ feats scratch
__device__ float g_spval[BHn*Rn*8];               // sparse A values (pre-gate)
__device__ int   g_spcol[BHn*Rn*8];               // sparse A column indices
__device__ int   g_spcnt[BHn*Rn];                 // nnz per row
__device__ float g_gap[BHn];                      // sum of rel per (b,h)
__device__ float g_maxA[BHn];                     // max kept rel value per (b,h)
__device__ float g_gate[BHn];                     // SE gate (0 or 1)
__device__ int   g_flag[BHn];                     // gate!=0 && maxA>0
__device__ float g_S[Tn+1];                       // S[t]=sum_i relu(gcn_b[i][t]); S[256]=mean

__global__ void k_nop() {}

// ---------------- K1: qk = x @ [Wq;Wk]^T  (tf32 HMMA) ---------------------
#define XPAD 40
__global__ void __launch_bounds__(256)
k_qkproj(const float* __restrict__ x,
         const float* __restrict__ Wq, const float* __restrict__ Wk)
{
    __shared__ float Xs[128 * XPAD];
    __shared__ float Ws[128 * XPAD];

    int tid = threadIdx.x;
    int wid = tid >> 5;
    int m0 = blockIdx.x * 128, n0 = blockIdx.y * 128;
    int wm = wid >> 2;          // 0..1 : 64-row slice
    int wn = wid & 3;           // 0..3 : 32-col slice

    const float* Wbase = (n0 < 256) ? (Wq + (size_t)n0 * 256)
                                    : (Wk + (size_t)(n0 - 256) * 256);
    const float* Xbase = x + (size_t)m0 * 256;

    wmma::fragment<wmma::accumulator, 16, 16, 8, float> acc[4][2];
    #pragma unroll
    for (int i = 0; i < 4; i++)
        #pragma unroll
        for (int j = 0; j < 2; j++)
            wmma::fill_fragment(acc[i][j], 0.0f);

    for (int k0 = 0; k0 < 256; k0 += 32) {
        #pragma unroll
        for (int i = 0; i < 4; i++) {
            int idx = tid + i * 256;
            int row = idx >> 3;
            int c4  = (idx & 7) * 4;
            float4 xv = *(const float4*)(Xbase + (size_t)row * 256 + k0 + c4);
            float4 wv = *(const float4*)(Wbase + (size_t)row * 256 + k0 + c4);
            // convert to tf32 ONCE here (loads below skip per-fragment convert)
            xv.x = wmma::__float_to_tf32(xv.x); xv.y = wmma::__float_to_tf32(xv.y);
            xv.z = wmma::__float_to_tf32(xv.z); xv.w = wmma::__float_to_tf32(xv.w);
            wv.x = wmma::__float_to_tf32(wv.x); wv.y = wmma::__float_to_tf32(wv.y);
            wv.z = wmma::__float_to_tf32(wv.z); wv.w = wmma::__float_to_tf32(wv.w);
            *(float4*)&Xs[row * XPAD + c4] = xv;
            *(float4*)&Ws[row * XPAD + c4] = wv;
        }
        __syncthreads();

        #pragma unroll
        for (int kk = 0; kk < 32; kk += 8) {
            wmma::fragment<wmma::matrix_a, 16, 16, 8, wmma::precision::tf32, wmma::row_major> af[4];
            wmma::fragment<wmma::matrix_b, 16, 16, 8, wmma::precision::tf32, wmma::col_major> bf[2];
            #pragma unroll
            for (int i = 0; i < 4; i++)
                wmma::load_matrix_sync(af[i], &Xs[(wm * 64 + i * 16) * XPAD + kk], XPAD);
            #pragma unroll
            for (int j = 0; j < 2; j++)
                wmma::load_matrix_sync(bf[j], &Ws[(wn * 32 + j * 16) * XPAD + kk], XPAD);
            #pragma unroll
            for (int i = 0; i < 4; i++)
                #pragma unroll
                for (int j = 0; j < 2; j++)
                    wmma::mma_sync(acc[i][j], af[i], bf[j], acc[i][j]);
        }
        __syncthreads();
    }

    #pragma unroll
    for (int i = 0; i < 4; i++)
        #pragma unroll
        for (int j = 0; j < 2; j++) {
            float* dst = g_qk + (size_t)(m0 + wm * 64 + i * 16) * NQK
                              + n0 + wn * 32 + j * 16;
            wmma::store_matrix_sync(dst, acc[i][j], NQK, wmma::mem_row_major);
        }
}

// ---------------- K2: fused rel/softmax; rank only when row survives ------
// KEY: after softmax, row max == 1/se. So rinv <= thr  =>  relu(p - thr) == 0
// for the whole row (exact). Skip threshold/rank/writes except spcnt=0.
#define SQS 36
__global__ void __launch_bounds__(256, 3)
k_attn(const float* __restrict__ thr_p,
       const float* __restrict__ bq, const float* __restrict__ bk)
{
    __shared__ float sq[132 * SQS];
    __shared__ float sk[132 * SQS];
    __shared__ float s_gap[8], s_max[8];

    int bh = blockIdx.x, b = bh >> 3, h = bh & 7;
    int tid = threadIdx.x, lane = tid & 31, w = tid >> 5;
    const float thr = *thr_p;

    // load q,k + bias into smem (rows 130,131 zero)
    for (int e = tid; e < 132 * Qd; e += 256) {
        int r = e >> 5, i = e & 31;
        float qv = 0.f, kv = 0.f;
        if (r < Rn) {
            size_t rowb = (size_t)(b * Rn + r) * NQK + h * 32;
            qv = g_qk[rowb + i]       + bq[h * 32 + i];
            kv = g_qk[rowb + 256 + i] + bk[h * 32 + i];
        }
        sq[r * SQS + i] = qv;
        sk[r * SQS + i] = kv;
    }
    __syncthreads();

    float gapAcc = 0.f, maxAcc = 0.f;
    const float sc = 0.17677669529663687f;   // 1/sqrt(32)
    const int cols1 = 4, cols2 = 5, cols3 = 6, cols4 = 7, cols5 = 8;

    // per-lane k row indices for each column block (clamped to zero row)
    int sjb[5];
    #pragma unroll
    for (int jb = 0; jb < 5; jb++) {
        int s = jb * 32 + lane; sjb[jb] = (s > 131) ? 131 : s;
    }
    bool val4 = (lane < 2);   // jb=4 true columns: 128,129 only

    for (int g = w; g < 33; g += 8) {
        int r0 = g * 4;
        float acc[4][5];
        #pragma unroll
        for (int rr = 0; rr < 4; rr++)
            #pragma unroll
            for (int jb = 0; jb < 5; jb++) acc[rr][jb] = 0.f;

        // QK^T for 4 rows; q loaded once per i4 (broadcast), k once per jb
        #pragma unroll
        for (int i4 = 0; i4 < 32; i4 += 4) {
            float4 qv[4];
            #pragma unroll
            for (int rr = 0; rr < 4; rr++)
                qv[rr] = *(const float4*)&sq[(r0 + rr) * SQS + i4];
            #pragma unroll
            for (int jb = 0; jb < 5; jb++) {
                float4 kv = *(const float4*)&sk[sjb[jb] * SQS + i4];
                #pragma unroll
                for (int rr = 0; rr < 4; rr++) {
                    float a = acc[rr][jb];
                    a = fmaf(qv[rr].x, kv.x, a);
                    a = fmaf(qv[rr].y, kv.y, a);
                    a = fmaf(qv[rr].z, kv.z, a);
                    a = fmaf(qv[rr].w, kv.w, a);
                    acc[rr][jb] = a;
                }
            }
        }

        #pragma unroll
        for (int rr = 0; rr < 4; rr++) {
            int r = r0 + rr;
            if (r >= Rn) continue;

            float v0 = acc[rr][0] * sc, v1 = acc[rr][1] * sc,
                  v2 = acc[rr][2] * sc, v3 = acc[rr][3] * sc,
                  v4 = acc[rr][4] * sc;
            // softmax max + denom
            float m = fmaxf(fmaxf(fmaxf(v0, v1), fmaxf(v2, v3)),
                            val4 ? v4 : -1e30f);
            #pragma unroll
            for (int o = 16; o; o >>= 1) m = fmaxf(m, __shfl_xor_sync(~0u, m, o));
            float e0 = __expf(v0 - m), e1 = __expf(v1 - m),
                  e2 = __expf(v2 - m), e3 = __expf(v3 - m);
            float e4 = val4 ? __expf(v4 - m) : 0.f;
            float se = e0 + e1 + e2 + e3 + e4;
            #pragma unroll
            for (int o = 16; o; o >>= 1) se += __shfl_xor_sync(~0u, se, o);
            float rinv = 1.f / se;

            if (rinv <= thr) {
                // row max of softmax == rinv <= thr  =>  entire row zero (exact)
                if (lane == 0) g_spcnt[bh * Rn + r] = 0;
                continue;
            }

            // ---- rare full path ----
            v0 = fmaxf(fmaf(e0, rinv, -thr), 0.f);
            v1 = fmaxf(fmaf(e1, rinv, -thr), 0.f);
            v2 = fmaxf(fmaf(e2, rinv, -thr), 0.f);
            v3 = fmaxf(fmaf(e3, rinv, -thr), 0.f);
            v4 = val4 ? fmaxf(fmaf(e4, rinv, -thr), 0.f) : 0.f;
            float gs = v0 + v1 + v2 + v3 + v4;
            #pragma unroll
            for (int o = 16; o; o >>= 1) gs += __shfl_xor_sync(~0u, gs, o);

            // ranks of columns {0,4,5,6,7,8}
            float c0 = __shfl_sync(~0u, v0, 0);
            float c1 = __shfl_sync(~0u, v0, cols1);
            float c2 = __shfl_sync(~0u, v0, cols2);
            float c3 = __shfl_sync(~0u, v0, cols3);
            float c4c = __shfl_sync(~0u, v0, cols4);
            float c5 = __shfl_sync(~0u, v0, cols5);

            unsigned p0 = 0, p1 = 0;
            #pragma unroll
            for (int jb = 0; jb < 5; jb++) {
                int j = jb * 32 + lane;
                float vv = (jb == 0) ? v0 : (jb == 1) ? v1 : (jb == 2) ? v2
                         : (jb == 3) ? v3 : v4;
                p0 += (vv > c0)                                   ? 1u        : 0u;
                p0 += ((vv > c1) || (vv == c1 && j < cols1))      ? (1u<<8)   : 0u;
                p0 += ((vv > c2) || (vv == c2 && j < cols2))      ? (1u<<16)  : 0u;
                p0 += ((vv > c3) || (vv == c3 && j < cols3))      ? (1u<<24)  : 0u;
                p1 += ((vv > c4c)|| (vv == c4c&& j < cols4))      ? 1u        : 0u;
                p1 += ((vv > c5) || (vv == c5 && j < cols5))      ? (1u<<8)   : 0u;
            }
            #pragma unroll
            for (int o = 16; o; o >>= 1) {
                p0 += __shfl_xor_sync(~0u, p0, o);
                p1 += __shfl_xor_sync(~0u, p1, o);
            }
            int myp = (lane < 4) ? (int)((p0 >> (8 * lane)) & 255u)
                                 : (int)((p1 >> (8 * (lane - 4))) & 255u);
            unsigned ball = __ballot_sync(~0u, (lane < 6) && (myp == r));
            int cnt = 6;
            if (!ball) { if (lane == 6) myp = r; cnt = 7; }

            int base = (bh * Rn + r) * 8;
            float rmax = 0.f;
            for (int i = 0; i < cnt; i++) {
                int p = __shfl_sync(~0u, myp, i);
                int jbp = p >> 5;
                float av = (jbp == 0) ? v0 : (jbp == 1) ? v1 : (jbp == 2) ? v2
                         : (jbp == 3) ? v3 : v4;
                float vv = __shfl_sync(~0u, av, p & 31);
                if (lane == 0) { g_spcol[base + i] = p; g_spval[base + i] = vv; }
                rmax = fmaxf(rmax, vv);
            }
            if (lane == 0) {
                g_spcnt[bh * Rn + r] = cnt;
                gapAcc += gs;
                maxAcc = fmaxf(maxAcc, rmax);
            }
        }
    }
    if (lane == 0) { s_gap[w] = gapAcc; s_max[w] = maxAcc; }
    __syncthreads();
    if (tid == 0) {
        float gsum = 0.f, mx = 0.f;
        #pragma unroll
        for (int i = 0; i < 8; i++) { gsum += s_gap[i]; mx = fmaxf(mx, s_max[i]); }
        g_gap[bh] = gsum; g_maxA[bh] = mx;
    }
}

// ---------------- K3: SE gate + flags -------------------------------------
__global__ void k_gate(const float* __restrict__ seW1, const float* __restrict__ seb1,
                       const float* __restrict__ seW2, const float* __restrict__ seb2)
{
    int b = blockIdx.x;
    if (threadIdx.x) return;
    float g[8];
    #pragma unroll
    for (int h = 0; h < 8; h++) g[h] = g_gap[b * 8 + h] * (1.f / 16900.f);
    float hd[4];
    #pragma unroll
    for (int j = 0; j < 4; j++) {
        float a = seb1[j];
        #pragma unroll
        for (int h = 0; h < 8; h++) a = fmaf(seW1[j * 8 + h], g[h], a);
        hd[j] = fmaxf(a, 0.f);
    }
    #pragma unroll
    for (int i = 0; i < 8; i++) {
        float z = seb2[i];
        #pragma unroll
        for (int j = 0; j < 4; j++) z = fmaf(seW2[i * 4 + j], hd[j], z);
        float gt = floorf(1.f / (1.f + expf(-z)));   // .long() truncation
        g_gate[b * 8 + i] = gt;
        g_flag[b * 8 + i] = (gt != 0.f) && (g_maxA[b * 8 + i] > 0.f);
    }
}

// ---------------- Kprep: S[t] = sum_i relu(gcn_b[i][t]) -------------------
__global__ void k_prep(const float* __restrict__ gcn_b)
{
    __shared__ float red[256];
    int t = threadIdx.x;
    float s = 0.f;
    #pragma unroll
    for (int i = 0; i < 8; i++) s += fmaxf(gcn_b[i * 256 + t], 0.f);
    g_S[t] = s;
    red[t] = s; __syncthreads();
    for (int o = 128; o; o >>= 1) { if (t < o) red[t] += red[t + o]; __syncthreads(); }
    if (t == 0) g_S[256] = red[0] * (1.f / 256.f);
}

// ---------------- GCN: all 8 layers, one block per (b,h), flag-guarded ----
__global__ void k_gcnall(const float* __restrict__ x,
                         const float* __restrict__ gcnW, const float* __restrict__ gcnb)
{
    int bh = blockIdx.x;
    if (!g_flag[bh]) return;
    int b = bh >> 3;
    float gt = g_gate[bh];
    size_t base = (size_t)bh * Rn * Tn;
    const float* xb = x + (size_t)b * Rn * Tn;

    for (int e = threadIdx.x; e < Rn * Tn; e += 256) g_feats[base + e] = xb[e];
    __syncthreads();

    for (int L = 0; L < 8; L++) {
        const float* W    = gcnW + (size_t)L * Tn * Tn;
        const float* bias = gcnb + L * Tn;
        for (int e = threadIdx.x; e < Rn * Tn; e += 256) {
            int r = e >> 8, t = e & 255;
            int cnt = g_spcnt[bh * Rn + r];
            int sb  = (bh * Rn + r) * 8;
            float a = 0.f;
            for (int i = 0; i < cnt; i++)
                a = fmaf(g_spval[sb + i],
                         g_feats[base + (size_t)g_spcol[sb + i] * Tn + t], a);
            g_agg[base + e] = a * gt;
        }
        __syncthreads();
        for (int e = threadIdx.x; e < Rn * Tn; e += 256) {
            int r = e >> 8, t = e & 255;
            float acc = bias[t];
            const float* ag = g_agg + base + (size_t)r * Tn;
            const float* wr = W + (size_t)t * Tn;
            for (int u = 0; u < Tn; u++) acc = fmaf(ag[u], wr[u], acc);
            g_feats[base + e] = fmaxf(acc, 0.f) + g_feats[base + e];
        }
        __syncthreads();
    }
}

// ---------------- K5: fusion + pool + MLP head ----------------------------
__global__ void k_head(const float* __restrict__ x,
                       const float* __restrict__ fw, const float* __restrict__ fb,
                       const float* __restrict__ W1, const float* __restrict__ b1,
                       const float* __restrict__ W2, const float* __restrict__ b2,
                       const float* __restrict__ W3, const float* __restrict__ b3,
                       float* __restrict__ out)
{
    int b = blockIdx.x;
    int tid = threadIdx.x, lane = tid & 31, w = tid >> 5;
    __shared__ float pooled[132], sh1[64], sh2[16];
    __shared__ float swf[8];
    __shared__ int   sfl[8];
    if (tid < 8) { swf[tid] = fw[tid]; sfl[tid] = g_flag[b * 8 + tid]; }
    __syncthreads();
    float meanS = g_S[256], fbv = *fb;

    for (int r = w; r < Rn; r += 8) {
        const float* xr = x + ((size_t)b * Rn + r) * Tn;
        float sx = 0.f;
        for (int t = lane; t < Tn; t += 32) sx += xr[t];
        #pragma unroll
        for (int o = 16; o; o >>= 1) sx += __shfl_xor_sync(~0u, sx, o);
        float mx = sx * (1.f / 256.f);
        float acc = fbv;
        #pragma unroll
        for (int h = 0; h < 8; h++) {
            if (sfl[h]) {
                const float* fr = g_feats + ((size_t)(b * 8 + h) * Rn + r) * Tn;
                float sf = 0.f;
                for (int t = lane; t < Tn; t += 32) sf += fr[t];
                #pragma unroll
                for (int o = 16; o; o >>= 1) sf += __shfl_xor_sync(~0u, sf, o);
                acc = fmaf(swf[h], sf * (1.f / 256.f), acc);
            } else {
                acc = fmaf(swf[h], mx + meanS, acc);   // closed form: feats = x + S
            }
        }
        if (lane == 0) pooled[r] = acc;
    }
    __syncthreads();
    if (tid < 64) {
        float a = b1[tid];
        for (int r = 0; r < Rn; r++) a = fmaf(W1[tid * Rn + r], pooled[r], a);
        sh1[tid] = fmaxf(a, 0.f);
    }
    __syncthreads();
    if (tid < 16) {
        float a = b2[tid];
        #pragma unroll
        for (int j = 0; j < 64; j++) a = fmaf(W2[tid * 64 + j], sh1[j], a);
        sh2[tid] = fmaxf(a, 0.f);
    }
    __syncthreads();
    if (tid < 5) {
        float a = b3[tid];
        #pragma unroll
        for (int j = 0; j < 16; j++) a = fmaf(W3[tid * 16 + j], sh2[j], a);
        out[b * 5 + tid] = fmaxf(a, 0.f);
    }
}

// ---------------- launch ---------------------------------------------------
extern "C" void kernel_launch(void* const* d_in, const int* in_sizes, int n_in,
                              void* d_out, int out_size)
{
    const float* x    = (const float*)d_in[0];
    const float* Wq   = (const float*)d_in[1];
    const float* bq   = (const float*)d_in[2];
    const float* Wk   = (const float*)d_in[3];
    const float* bk   = (const float*)d_in[4];
    const float* thr  = (const float*)d_in[5];
    const float* seW1 = (const float*)d_in[6];
    const float* seb1 = (const float*)d_in[7];
    const float* seW2 = (const float*)d_in[8];
    const float* seb2 = (const float*)d_in[9];
    const float* gcnW = (const float*)d_in[10];
    const float* gcnb = (const float*)d_in[11];
    const float* fw   = (const float*)d_in[12];
    const float* fb   = (const float*)d_in[13];
    const float* W1   = (const float*)d_in[14];
    const float* b1   = (const float*)d_in[15];
    const float* W2   = (const float*)d_in[16];
    const float* b2   = (const float*)d_in[17];
    const float* W3   = (const float*)d_in[18];
    const float* b3   = (const float*)d_in[19];
    float* out = (float*)d_out;

    dim3 g1(Mn / 128, NQK / 128);
    k_qkproj<<<g1, 256>>>(x, Wq, Wk);                    // launch 1
    k_prep<<<1, 256>>>(gcnb);                            // launch 2
    k_nop<<<1, 32>>>();                                  // launch 3
    k_attn<<<BHn, 256>>>(thr, bq, bk);                   // launch 4 <- ncu capture
    k_gate<<<Bn, 32>>>(seW1, seb1, seW2, seb2);          // launch 5
    k_gcnall<<<BHn, 256>>>(x, gcnW, gcnb);               // launch 6
    k_head<<<Bn, 256>>>(x, fw, fb, W1, b1, W2, b2, W3, b3, out);  // launch 7
}

// round 6
// speedup vs baseline: 1.4006x; 1.0257x over previous
#include <cuda_runtime.h>
#include <mma.h>
#include <math.h>

using namespace nvcuda;

#define Bn   128
#define Hn   8
#define Rn   130
#define Tn   256
#define Qd   32
#define BHn  (Bn*Hn)     /* 1024 */
#define Mn   (Bn*Rn)     /* 16640 */
#define NQK  512

// ---------------- device scratch (no allocations allowed) ----------------
__device__ float g_qk[(size_t)Mn*NQK];            // q|k projections (NO bias), [M,512]
__device__ float g_feats[(size_t)BHn*Rn*Tn];      // GCN features (flagged heads only)
__device__ float g_agg[(size_t)BHn*Rn*Tn];        // sparse A @ feats scratch
__device__ float g_spval[BHn*Rn*8];               // sparse A values (pre-gate)
__device__ int   g_spcol[BHn*Rn*8];               // sparse A column indices
__device__ int   g_spcnt[BHn*Rn];                 // nnz per row
__device__ float g_gap[BHn];                      // sum of rel per (b,h)
__device__ float g_maxA[BHn];                     // max kept rel value per (b,h)
__device__ float g_gate[BHn];                     // SE gate (0 or 1)
__device__ int   g_flag[BHn];                     // gate!=0 && maxA>0
__device__ float g_S[Tn+1];                       // S[t]=sum_i relu(gcn_b[i][t]); S[256]=mean

__global__ void k_nop() {}

// ---------------- K1: qk = x @ [Wq;Wk]^T  (tf32 HMMA) ---------------------
#define XPAD 40
__global__ void __launch_bounds__(256)
k_qkproj(const float* __restrict__ x,
         const float* __restrict__ Wq, const float* __restrict__ Wk)
{
    __shared__ float Xs[128 * XPAD];
    __shared__ float Ws[128 * XPAD];

    int tid = threadIdx.x;
    int wid = tid >> 5;
    int m0 = blockIdx.x * 128, n0 = blockIdx.y * 128;
    int wm = wid >> 2;          // 0..1 : 64-row slice
    int wn = wid & 3;           // 0..3 : 32-col slice

    const float* Wbase = (n0 < 256) ? (Wq + (size_t)n0 * 256)
                                    : (Wk + (size_t)(n0 - 256) * 256);
    const float* Xbase = x + (size_t)m0 * 256;

    wmma::fragment<wmma::accumulator, 16, 16, 8, float> acc[4][2];
    #pragma unroll
    for (int i = 0; i < 4; i++)
        #pragma unroll
        for (int j = 0; j < 2; j++)
            wmma::fill_fragment(acc[i][j], 0.0f);

    for (int k0 = 0; k0 < 256; k0 += 32) {
        #pragma unroll
        for (int i = 0; i < 4; i++) {
            int idx = tid + i * 256;
            int row = idx >> 3;
            int c4  = (idx & 7) * 4;
            float4 xv = *(const float4*)(Xbase + (size_t)row * 256 + k0 + c4);
            float4 wv = *(const float4*)(Wbase + (size_t)row * 256 + k0 + c4);
            xv.x = wmma::__float_to_tf32(xv.x); xv.y = wmma::__float_to_tf32(xv.y);
            xv.z = wmma::__float_to_tf32(xv.z); xv.w = wmma::__float_to_tf32(xv.w);
            wv.x = wmma::__float_to_tf32(wv.x); wv.y = wmma::__float_to_tf32(wv.y);
            wv.z = wmma::__float_to_tf32(wv.z); wv.w = wmma::__float_to_tf32(wv.w);
            *(float4*)&Xs[row * XPAD + c4] = xv;
            *(float4*)&Ws[row * XPAD + c4] = wv;
        }
        __syncthreads();

        #pragma unroll
        for (int kk = 0; kk < 32; kk += 8) {
            wmma::fragment<wmma::matrix_a, 16, 16, 8, wmma::precision::tf32, wmma::row_major> af[4];
            wmma::fragment<wmma::matrix_b, 16, 16, 8, wmma::precision::tf32, wmma::col_major> bf[2];
            #pragma unroll
            for (int i = 0; i < 4; i++)
                wmma::load_matrix_sync(af[i], &Xs[(wm * 64 + i * 16) * XPAD + kk], XPAD);
            #pragma unroll
            for (int j = 0; j < 2; j++)
                wmma::load_matrix_sync(bf[j], &Ws[(wn * 32 + j * 16) * XPAD + kk], XPAD);
            #pragma unroll
            for (int i = 0; i < 4; i++)
                #pragma unroll
                for (int j = 0; j < 2; j++)
                    wmma::mma_sync(acc[i][j], af[i], bf[j], acc[i][j]);
        }
        __syncthreads();
    }

    #pragma unroll
    for (int i = 0; i < 4; i++)
        #pragma unroll
        for (int j = 0; j < 2; j++) {
            float* dst = g_qk + (size_t)(m0 + wm * 64 + i * 16) * NQK
                              + n0 + wn * 32 + j * 16;
            wmma::store_matrix_sync(dst, acc[i][j], NQK, wmma::mem_row_major);
        }
}

// ---------------- K2: fused rel/softmax; interleaved 4-row reductions -----
// Row max of softmax == 1/se. rinv <= thr => relu(softmax - thr) == 0 exactly.
#define SQS 36
__global__ void __launch_bounds__(256, 4)
k_attn(const float* __restrict__ thr_p,
       const float* __restrict__ bq, const float* __restrict__ bk)
{
    __shared__ float sq[132 * SQS];
    __shared__ float sk[132 * SQS];
    __shared__ float s_gap[8], s_max[8];

    int bh = blockIdx.x, b = bh >> 3, h = bh & 7;
    int tid = threadIdx.x, lane = tid & 31, w = tid >> 5;
    const float thr = *thr_p;

    for (int e = tid; e < 132 * Qd; e += 256) {
        int r = e >> 5, i = e & 31;
        float qv = 0.f, kv = 0.f;
        if (r < Rn) {
            size_t rowb = (size_t)(b * Rn + r) * NQK + h * 32;
            qv = g_qk[rowb + i]       + bq[h * 32 + i];
            kv = g_qk[rowb + 256 + i] + bk[h * 32 + i];
        }
        sq[r * SQS + i] = qv;
        sk[r * SQS + i] = kv;
    }
    __syncthreads();

    float gapAcc = 0.f, maxAcc = 0.f;
    const float sc = 0.17677669529663687f;   // 1/sqrt(32)
    const int cols1 = 4, cols2 = 5, cols3 = 6, cols4 = 7, cols5 = 8;

    int sjb[5];
    #pragma unroll
    for (int jb = 0; jb < 5; jb++) {
        int s = jb * 32 + lane; sjb[jb] = (s > 131) ? 131 : s;
    }
    bool val4 = (lane < 2);   // jb=4 true columns: 128,129 only

    for (int g = w; g < 33; g += 8) {
        int r0 = g * 4;
        float acc[4][5];
        #pragma unroll
        for (int rr = 0; rr < 4; rr++)
            #pragma unroll
            for (int jb = 0; jb < 5; jb++) acc[rr][jb] = 0.f;

        // QK^T for 4 rows
        #pragma unroll
        for (int i4 = 0; i4 < 32; i4 += 4) {
            float4 qv[4];
            #pragma unroll
            for (int rr = 0; rr < 4; rr++)
                qv[rr] = *(const float4*)&sq[(r0 + rr) * SQS + i4];
            #pragma unroll
            for (int jb = 0; jb < 5; jb++) {
                float4 kv = *(const float4*)&sk[sjb[jb] * SQS + i4];
                #pragma unroll
                for (int rr = 0; rr < 4; rr++) {
                    float a = acc[rr][jb];
                    a = fmaf(qv[rr].x, kv.x, a);
                    a = fmaf(qv[rr].y, kv.y, a);
                    a = fmaf(qv[rr].z, kv.z, a);
                    a = fmaf(qv[rr].w, kv.w, a);
                    acc[rr][jb] = a;
                }
            }
        }

        // scale
        #pragma unroll
        for (int rr = 0; rr < 4; rr++)
            #pragma unroll
            for (int jb = 0; jb < 5; jb++) acc[rr][jb] *= sc;

        // interleaved max reduction (4 independent chains)
        float lm[4];
        #pragma unroll
        for (int rr = 0; rr < 4; rr++)
            lm[rr] = fmaxf(fmaxf(fmaxf(acc[rr][0], acc[rr][1]),
                                 fmaxf(acc[rr][2], acc[rr][3])),
                           val4 ? acc[rr][4] : -1e30f);
        #pragma unroll
        for (int o = 16; o; o >>= 1) {
            #pragma unroll
            for (int rr = 0; rr < 4; rr++)
                lm[rr] = fmaxf(lm[rr], __shfl_xor_sync(~0u, lm[rr], o));
        }

        // exp in place (acc becomes exp values), interleaved sum reduction
        float es[4];
        #pragma unroll
        for (int rr = 0; rr < 4; rr++) {
            acc[rr][0] = __expf(acc[rr][0] - lm[rr]);
            acc[rr][1] = __expf(acc[rr][1] - lm[rr]);
            acc[rr][2] = __expf(acc[rr][2] - lm[rr]);
            acc[rr][3] = __expf(acc[rr][3] - lm[rr]);
            acc[rr][4] = val4 ? __expf(acc[rr][4] - lm[rr]) : 0.f;
            es[rr] = acc[rr][0] + acc[rr][1] + acc[rr][2] + acc[rr][3] + acc[rr][4];
        }
        #pragma unroll
        for (int o = 16; o; o >>= 1) {
            #pragma unroll
            for (int rr = 0; rr < 4; rr++)
                es[rr] += __shfl_xor_sync(~0u, es[rr], o);
        }

        // batched dead-row handling (values uniform across warp)
        unsigned dm = 0;
        #pragma unroll
        for (int rr = 0; rr < 4; rr++)
            if (1.f <= thr * es[rr]) dm |= (1u << rr);   // rinv <= thr
        if (lane < 4) {
            int r = r0 + lane;
            if (r < Rn && ((dm >> lane) & 1u)) g_spcnt[bh * Rn + r] = 0;
        }

        if (dm == 15u) continue;   // all 4 rows dead (common case)

        // ---- rare full path ----
        #pragma unroll
        for (int rr = 0; rr < 4; rr++) {
            int r = r0 + rr;
            if (r >= Rn || ((dm >> rr) & 1u)) continue;
            float rinv = 1.f / es[rr];
            float v0 = fmaxf(fmaf(acc[rr][0], rinv, -thr), 0.f);
            float v1 = fmaxf(fmaf(acc[rr][1], rinv, -thr), 0.f);
            float v2 = fmaxf(fmaf(acc[rr][2], rinv, -thr), 0.f);
            float v3 = fmaxf(fmaf(acc[rr][3], rinv, -thr), 0.f);
            float v4 = val4 ? fmaxf(fmaf(acc[rr][4], rinv, -thr), 0.f) : 0.f;
            float gs = v0 + v1 + v2 + v3 + v4;
            #pragma unroll
            for (int o = 16; o; o >>= 1) gs += __shfl_xor_sync(~0u, gs, o);

            float c0 = __shfl_sync(~0u, v0, 0);
            float c1 = __shfl_sync(~0u, v0, cols1);
            float c2 = __shfl_sync(~0u, v0, cols2);
            float c3 = __shfl_sync(~0u, v0, cols3);
            float c4c = __shfl_sync(~0u, v0, cols4);
            float c5 = __shfl_sync(~0u, v0, cols5);

            unsigned p0 = 0, p1 = 0;
            #pragma unroll
            for (int jb = 0; jb < 5; jb++) {
                int j = jb * 32 + lane;
                float vv = (jb == 0) ? v0 : (jb == 1) ? v1 : (jb == 2) ? v2
                         : (jb == 3) ? v3 : v4;
                p0 += (vv > c0)                                   ? 1u        : 0u;
                p0 += ((vv > c1) || (vv == c1 && j < cols1))      ? (1u<<8)   : 0u;
                p0 += ((vv > c2) || (vv == c2 && j < cols2))      ? (1u<<16)  : 0u;
                p0 += ((vv > c3) || (vv == c3 && j < cols3))      ? (1u<<24)  : 0u;
                p1 += ((vv > c4c)|| (vv == c4c&& j < cols4))      ? 1u        : 0u;
                p1 += ((vv > c5) || (vv == c5 && j < cols5))      ? (1u<<8)   : 0u;
            }
            #pragma unroll
            for (int o = 16; o; o >>= 1) {
                p0 += __shfl_xor_sync(~0u, p0, o);
                p1 += __shfl_xor_sync(~0u, p1, o);
            }
            int myp = (lane < 4) ? (int)((p0 >> (8 * lane)) & 255u)
                                 : (int)((p1 >> (8 * (lane - 4))) & 255u);
            unsigned ball = __ballot_sync(~0u, (lane < 6) && (myp == r));
            int cnt = 6;
            if (!ball) { if (lane == 6) myp = r; cnt = 7; }

            int base = (bh * Rn + r) * 8;
            float rmax = 0.f;
            for (int i = 0; i < cnt; i++) {
                int p = __shfl_sync(~0u, myp, i);
                int jbp = p >> 5;
                float av = (jbp == 0) ? v0 : (jbp == 1) ? v1 : (jbp == 2) ? v2
                         : (jbp == 3) ? v3 : v4;
                float vv = __shfl_sync(~0u, av, p & 31);
                if (lane == 0) { g_spcol[base + i] = p; g_spval[base + i] = vv; }
                rmax = fmaxf(rmax, vv);
            }
            if (lane == 0) {
                g_spcnt[bh * Rn + r] = cnt;
                gapAcc += gs;
                maxAcc = fmaxf(maxAcc, rmax);
            }
        }
    }
    if (lane == 0) { s_gap[w] = gapAcc; s_max[w] = maxAcc; }
    __syncthreads();
    if (tid == 0) {
        float gsum = 0.f, mx = 0.f;
        #pragma unroll
        for (int i = 0; i < 8; i++) { gsum += s_gap[i]; mx = fmaxf(mx, s_max[i]); }
        g_gap[bh] = gsum; g_maxA[bh] = mx;
    }
}

// ---------------- K3: SE gate + flags -------------------------------------
__global__ void k_gate(const float* __restrict__ seW1, const float* __restrict__ seb1,
                       const float* __restrict__ seW2, const float* __restrict__ seb2)
{
    int b = blockIdx.x;
    if (threadIdx.x) return;
    float g[8];
    #pragma unroll
    for (int h = 0; h < 8; h++) g[h] = g_gap[b * 8 + h] * (1.f / 16900.f);
    float hd[4];
    #pragma unroll
    for (int j = 0; j < 4; j++) {
        float a = seb1[j];
        #pragma unroll
        for (int h = 0; h < 8; h++) a = fmaf(seW1[j * 8 + h], g[h], a);
        hd[j] = fmaxf(a, 0.f);
    }
    #pragma unroll
    for (int i = 0; i < 8; i++) {
        float z = seb2[i];
        #pragma unroll
        for (int j = 0; j < 4; j++) z = fmaf(seW2[i * 4 + j], hd[j], z);
        float gt = floorf(1.f / (1.f + expf(-z)));   // .long() truncation
        g_gate[b * 8 + i] = gt;
        g_flag[b * 8 + i] = (gt != 0.f) && (g_maxA[b * 8 + i] > 0.f);
    }
}

// ---------------- Kprep: S[t] = sum_i relu(gcn_b[i][t]) -------------------
__global__ void k_prep(const float* __restrict__ gcn_b)
{
    __shared__ float red[256];
    int t = threadIdx.x;
    float s = 0.f;
    #pragma unroll
    for (int i = 0; i < 8; i++) s += fmaxf(gcn_b[i * 256 + t], 0.f);
    g_S[t] = s;
    red[t] = s; __syncthreads();
    for (int o = 128; o; o >>= 1) { if (t < o) red[t] += red[t + o]; __syncthreads(); }
    if (t == 0) g_S[256] = red[0] * (1.f / 256.f);
}

// ---------------- GCN: all 8 layers, one block per (b,h), flag-guarded ----
__global__ void k_gcnall(const float* __restrict__ x,
                         const float* __restrict__ gcnW, const float* __restrict__ gcnb)
{
    int bh = blockIdx.x;
    if (!g_flag[bh]) return;
    int b = bh >> 3;
    float gt = g_gate[bh];
    size_t base = (size_t)bh * Rn * Tn;
    const float* xb = x + (size_t)b * Rn * Tn;

    for (int e = threadIdx.x; e < Rn * Tn; e += 256) g_feats[base + e] = xb[e];
    __syncthreads();

    for (int L = 0; L < 8; L++) {
        const float* W    = gcnW + (size_t)L * Tn * Tn;
        const float* bias = gcnb + L * Tn;
        for (int e = threadIdx.x; e < Rn * Tn; e += 256) {
            int r = e >> 8, t = e & 255;
            int cnt = g_spcnt[bh * Rn + r];
            int sb  = (bh * Rn + r) * 8;
            float a = 0.f;
            for (int i = 0; i < cnt; i++)
                a = fmaf(g_spval[sb + i],
                         g_feats[base + (size_t)g_spcol[sb + i] * Tn + t], a);
            g_agg[base + e] = a * gt;
        }
        __syncthreads();
        for (int e = threadIdx.x; e < Rn * Tn; e += 256) {
            int r = e >> 8, t = e & 255;
            float acc = bias[t];
            const float* ag = g_agg + base + (size_t)r * Tn;
            const float* wr = W + (size_t)t * Tn;
            for (int u = 0; u < Tn; u++) acc = fmaf(ag[u], wr[u], acc);
            g_feats[base + e] = fmaxf(acc, 0.f) + g_feats[base + e];
        }
        __syncthreads();
    }
}

// ---------------- K5: fusion + pool + MLP head ----------------------------
__global__ void k_head(const float* __restrict__ x,
                       const float* __restrict__ fw, const float* __restrict__ fb,
                       const float* __restrict__ W1, const float* __restrict__ b1,
                       const float* __restrict__ W2, const float* __restrict__ b2,
                       const float* __restrict__ W3, const float* __restrict__ b3,
                       float* __restrict__ out)
{
    int b = blockIdx.x;
    int tid = threadIdx.x, lane = tid & 31, w = tid >> 5;
    __shared__ float pooled[132], sh1[64], sh2[16];
    __shared__ float swf[8];
    __shared__ int   sfl[8];
    if (tid < 8) { swf[tid] = fw[tid]; sfl[tid] = g_flag[b * 8 + tid]; }
    __syncthreads();
    float meanS = g_S[256], fbv = *fb;

    for (int r = w; r < Rn; r += 8) {
        const float* xr = x + ((size_t)b * Rn + r) * Tn;
        float sx = 0.f;
        for (int t = lane; t < Tn; t += 32) sx += xr[t];
        #pragma unroll
        for (int o = 16; o; o >>= 1) sx += __shfl_xor_sync(~0u, sx, o);
        float mx = sx * (1.f / 256.f);
        float acc = fbv;
        #pragma unroll
        for (int h = 0; h < 8; h++) {
            if (sfl[h]) {
                const float* fr = g_feats + ((size_t)(b * 8 + h) * Rn + r) * Tn;
                float sf = 0.f;
                for (int t = lane; t < Tn; t += 32) sf += fr[t];
                #pragma unroll
                for (int o = 16; o; o >>= 1) sf += __shfl_xor_sync(~0u, sf, o);
                acc = fmaf(swf[h], sf * (1.f / 256.f), acc);
            } else {
                acc = fmaf(swf[h], mx + meanS, acc);   // closed form: feats = x + S
            }
        }
        if (lane == 0) pooled[r] = acc;
    }
    __syncthreads();
    if (tid < 64) {
        float a = b1[tid];
        for (int r = 0; r < Rn; r++) a = fmaf(W1[tid * Rn + r], pooled[r], a);
        sh1[tid] = fmaxf(a, 0.f);
    }
    __syncthreads();
    if (tid < 16) {
        float a = b2[tid];
        #pragma unroll
        for (int j = 0; j < 64; j++) a = fmaf(W2[tid * 64 + j], sh1[j], a);
        sh2[tid] = fmaxf(a, 0.f);
    }
    __syncthreads();
    if (tid < 5) {
        float a = b3[tid];
        #pragma unroll
        for (int j = 0; j < 16; j++) a = fmaf(W3[tid * 16 + j], sh2[j], a);
        out[b * 5 + tid] = fmaxf(a, 0.f);
    }
}

// ---------------- launch ---------------------------------------------------
extern "C" void kernel_launch(void* const* d_in, const int* in_sizes, int n_in,
                              void* d_out, int out_size)
{
    const float* x    = (const float*)d_in[0];
    const float* Wq   = (const float*)d_in[1];
    const float* bq   = (const float*)d_in[2];
    const float* Wk   = (const float*)d_in[3];
    const float* bk   = (const float*)d_in[4];
    const float* thr  = (const float*)d_in[5];
    const float* seW1 = (const float*)d_in[6];
    const float* seb1 = (const float*)d_in[7];
    const float* seW2 = (const float*)d_in[8];
    const float* seb2 = (const float*)d_in[9];
    const float* gcnW = (const float*)d_in[10];
    const float* gcnb = (const float*)d_in[11];
    const float* fw   = (const float*)d_in[12];
    const float* fb   = (const float*)d_in[13];
    const float* W1   = (const float*)d_in[14];
    const float* b1   = (const float*)d_in[15];
    const float* W2   = (const float*)d_in[16];
    const float* b2   = (const float*)d_in[17];
    const float* W3   = (const float*)d_in[18];
    const float* b3   = (const float*)d_in[19];
    float* out = (float*)d_out;

    dim3 g1(Mn / 128, NQK / 128);
    k_qkproj<<<g1, 256>>>(x, Wq, Wk);                    // launch 1
    k_prep<<<1, 256>>>(gcnb);                            // launch 2
    k_nop<<<1, 32>>>();                                  // launch 3
    k_attn<<<BHn, 256>>>(thr, bq, bk);                   // launch 4 <- ncu capture
    k_gate<<<Bn, 32>>>(seW1, seb1, seW2, seb2);          // launch 5
    k_gcnall<<<BHn, 256>>>(x, gcnW, gcnb);               // launch 6
    k_head<<<Bn, 256>>>(x, fw, fb, W1, b1, W2, b2, W3, b3, out);  // launch 7
}